// round 15
// baseline (speedup 1.0000x reference)
#include <cuda_runtime.h>
#include <cuda_bf16.h>
#include <cuda_fp16.h>
#include <cstdint>
#include <cstddef>

// ---------------- problem constants ----------------
#define D_MODEL 1024
#define N_LAYER 4
#define VOCAB   32000
#define D_STATE 16
#define D_INNER 2048
#define D_CONV  4
#define BATCH   2
#define SEQ     1024
#define M_ROWS  (BATCH * SEQ)     // 2048

// ---------------- scratch (device globals; no allocation allowed) ----------
__device__ float g_X  [M_ROWS * D_MODEL];
__device__ float g_H  [M_ROWS * D_INNER];
__device__ float g_RES[M_ROWS * D_INNER];
__device__ float g_U  [M_ROWS * D_INNER];
__device__ float g_B  [M_ROWS * D_STATE];
__device__ float g_C  [M_ROWS * D_STATE];
__device__ float g_dt [M_ROWS];

// bf16 hi/lo operand buffers (layers 0..2)
__device__ __nv_bfloat16 g_XNh[M_ROWS * D_MODEL], g_XNl[M_ROWS * D_MODEL];
__device__ __nv_bfloat16 g_Hh [M_ROWS * D_INNER], g_Hl [M_ROWS * D_INNER];
__device__ __nv_bfloat16 g_YRh[M_ROWS * D_INNER], g_YRl[M_ROWS * D_INNER];
__device__ __nv_bfloat16 g_Winh [N_LAYER * D_INNER * D_MODEL], g_Winl [N_LAYER * D_INNER * D_MODEL];
__device__ __nv_bfloat16 g_Wresh[N_LAYER * D_INNER * D_INNER], g_Wresl[N_LAYER * D_INNER * D_INNER];
__device__ __nv_bfloat16 g_Wouth[N_LAYER * D_MODEL * D_INNER], g_Woutl[N_LAYER * D_MODEL * D_INNER];

// fp16 buffers (lm_head + last layer)
__device__ __half g_EmbF [(size_t)VOCAB * D_MODEL];
__device__ __half g_XNf  [M_ROWS * D_MODEL];
__device__ __half g_Hf   [M_ROWS * D_INNER];
__device__ __half g_YRf  [M_ROWS * D_INNER];
__device__ __half g_WinF [D_INNER * D_MODEL];
__device__ __half g_WresF[D_INNER * D_INNER];
__device__ __half g_WoutF[D_MODEL * D_INNER];

// ---------------- small helpers ----------------
__device__ __forceinline__ float silu_f(float x) { return x / (1.f + __expf(-x)); }
__device__ __forceinline__ float softplus_f(float x) { return x > 20.f ? x : log1pf(__expf(x)); }

__device__ __forceinline__ uint32_t smem_addr_u32(const void* p) {
    uint32_t a;
    asm("{ .reg .u64 t; cvta.to.shared.u64 t, %1; cvt.u32.u64 %0, t; }" : "=r"(a) : "l"(p));
    return a;
}
__device__ __forceinline__ void cp16(uint32_t dst, const void* src) {
    asm volatile("cp.async.cg.shared.global [%0], [%1], 16;" :: "r"(dst), "l"(src));
}
__device__ __forceinline__ void cp_commit() {
    asm volatile("cp.async.commit_group;" ::: "memory");
}
template <int N>
__device__ __forceinline__ void cp_wait() {
    asm volatile("cp.async.wait_group %0;" :: "n"(N) : "memory");
}
__device__ __forceinline__ void ldsm4(uint32_t& r0, uint32_t& r1, uint32_t& r2, uint32_t& r3,
                                      uint32_t a) {
    asm volatile("ldmatrix.sync.aligned.m8n8.x4.shared.b16 {%0,%1,%2,%3}, [%4];"
                 : "=r"(r0), "=r"(r1), "=r"(r2), "=r"(r3) : "r"(a));
}
__device__ __forceinline__ void mma_bf16(float& d0, float& d1, float& d2, float& d3,
                                         uint32_t a0, uint32_t a1, uint32_t a2, uint32_t a3,
                                         uint32_t b0, uint32_t b1) {
    asm volatile(
        "mma.sync.aligned.m16n8k16.row.col.f32.bf16.bf16.f32 "
        "{%0,%1,%2,%3}, {%4,%5,%6,%7}, {%8,%9}, {%0,%1,%2,%3};"
        : "+f"(d0), "+f"(d1), "+f"(d2), "+f"(d3)
        : "r"(a0), "r"(a1), "r"(a2), "r"(a3), "r"(b0), "r"(b1));
}
__device__ __forceinline__ void mma_f16(float& d0, float& d1, float& d2, float& d3,
                                        uint32_t a0, uint32_t a1, uint32_t a2, uint32_t a3,
                                        uint32_t b0, uint32_t b1) {
    asm volatile(
        "mma.sync.aligned.m16n8k16.row.col.f32.f16.f16.f32 "
        "{%0,%1,%2,%3}, {%4,%5,%6,%7}, {%8,%9}, {%0,%1,%2,%3};"
        : "+f"(d0), "+f"(d1), "+f"(d2), "+f"(d3)
        : "r"(a0), "r"(a1), "r"(a2), "r"(a3), "r"(b0), "r"(b1));
}
__device__ __forceinline__ void split_bf16(float v, __nv_bfloat16& hi, __nv_bfloat16& lo) {
    hi = __float2bfloat16(v);
    lo = __float2bfloat16(v - __bfloat162float(hi));
}

// ---------------- fp32 -> bf16 hi/lo split (weights) --------------
__global__ void split_kernel(const float4* __restrict__ x,
                             __nv_bfloat162* __restrict__ hi,
                             __nv_bfloat162* __restrict__ lo, int n4) {
    int t = blockIdx.x * 256 + threadIdx.x;
    if (t >= n4) return;
    float4 v = x[t];
    __nv_bfloat16 a = __float2bfloat16(v.x), b = __float2bfloat16(v.y);
    __nv_bfloat16 c = __float2bfloat16(v.z), d = __float2bfloat16(v.w);
    hi[2 * t]     = __nv_bfloat162(a, b);
    hi[2 * t + 1] = __nv_bfloat162(c, d);
    lo[2 * t] = __nv_bfloat162(__float2bfloat16(v.x - __bfloat162float(a)),
                               __float2bfloat16(v.y - __bfloat162float(b)));
    lo[2 * t + 1] = __nv_bfloat162(__float2bfloat16(v.z - __bfloat162float(c)),
                                   __float2bfloat16(v.w - __bfloat162float(d)));
}

// ---------------- fp32 -> fp16 convert ----------------
__global__ void cvt_f16_kernel(const float4* __restrict__ x,
                               __half2* __restrict__ y, int n4) {
    int t = blockIdx.x * 256 + threadIdx.x;
    if (t >= n4) return;
    float4 v = x[t];
    y[2 * t]     = __floats2half2_rn(v.x, v.y);
    y[2 * t + 1] = __floats2half2_rn(v.z, v.w);
}

// ---------------- embedding gather ----------------
__global__ void embed_kernel(const float* __restrict__ emb,
                             const int* __restrict__ ids,
                             float* __restrict__ X) {
    int t = blockIdx.x * blockDim.x + threadIdx.x;
    int row = t >> 10, col = t & 1023;
    X[t] = emb[(size_t)ids[row] * D_MODEL + col];
}

// ---------------- rmsnorm -> bf16 hi/lo ----------------
__global__ void rmsnorm_kernel(const float* __restrict__ X,
                               const float* __restrict__ w,
                               __nv_bfloat16* __restrict__ outh,
                               __nv_bfloat16* __restrict__ outl) {
    int row = blockIdx.x;
    const float* x = X + (size_t)row * D_MODEL;
    float s = 0.f;
    for (int i = threadIdx.x; i < D_MODEL; i += 256) { float v = x[i]; s += v * v; }
    __shared__ float red[256];
    red[threadIdx.x] = s;
    __syncthreads();
    for (int o = 128; o; o >>= 1) {
        if (threadIdx.x < o) red[threadIdx.x] += red[threadIdx.x + o];
        __syncthreads();
    }
    float scale = rsqrtf(red[0] * (1.f / D_MODEL) + 1e-5f);
    for (int i = threadIdx.x; i < D_MODEL; i += 256) {
        float v = x[i] * scale * w[i];
        __nv_bfloat16 hi, lo;
        split_bf16(v, hi, lo);
        outh[(size_t)row * D_MODEL + i] = hi;
        outl[(size_t)row * D_MODEL + i] = lo;
    }
}

// ---------------- rmsnorm -> fp16 ----------------
__global__ void rmsnorm_f16_kernel(const float* __restrict__ X,
                                   const float* __restrict__ w,
                                   __half* __restrict__ outf) {
    int row = blockIdx.x;
    const float* x = X + (size_t)row * D_MODEL;
    float s = 0.f;
    for (int i = threadIdx.x; i < D_MODEL; i += 256) { float v = x[i]; s += v * v; }
    __shared__ float red[256];
    red[threadIdx.x] = s;
    __syncthreads();
    for (int o = 128; o; o >>= 1) {
        if (threadIdx.x < o) red[threadIdx.x] += red[threadIdx.x + o];
        __syncthreads();
    }
    float scale = rsqrtf(red[0] * (1.f / D_MODEL) + 1e-5f);
    for (int i = threadIdx.x; i < D_MODEL; i += 256)
        outf[(size_t)row * D_MODEL + i] = __float2half(x[i] * scale * w[i]);
}

// ---------------- depthwise causal conv + silu ----------------
__global__ void conv_kernel(const float* __restrict__ H,
                            const float* __restrict__ cw,
                            const float* __restrict__ cb,
                            float* __restrict__ Uo) {
    int t = blockIdx.x * blockDim.x + threadIdx.x;
    int d = t & (D_INNER - 1);
    int bl = t >> 11;
    int l = bl & (SEQ - 1);
    float acc = cb[d];
#pragma unroll
    for (int j = 0; j < D_CONV; j++) {
        int ll = l - (D_CONV - 1) + j;
        if (ll >= 0)
            acc += H[(size_t)(bl - l + ll) * D_INNER + d] * cw[d * D_CONV + j];
    }
    Uo[t] = silu_f(acc);
}

// ---------------- B, C, dt projections ----------------
__global__ void bc_kernel(const float* __restrict__ U,
                          const float* __restrict__ wB, const float* __restrict__ bB,
                          const float* __restrict__ wC, const float* __restrict__ bC,
                          const float* __restrict__ wdt, const float* __restrict__ bdt,
                          float* __restrict__ Bm, float* __restrict__ Cm,
                          float* __restrict__ dtb) {
    int bl = blockIdx.x;
    __shared__ float su[D_INNER];
    const float* u = U + (size_t)bl * D_INNER;
    for (int i = threadIdx.x; i < D_INNER; i += 256) su[i] = u[i];
    __syncthreads();
    int warp = threadIdx.x >> 5, lane = threadIdx.x & 31;
    for (int j = warp; j < 2 * D_STATE + 1; j += 8) {
        const float* w = (j < D_STATE) ? wB + (size_t)j * D_INNER
                       : (j < 2 * D_STATE) ? wC + (size_t)(j - D_STATE) * D_INNER
                       : wdt;
        float s = 0.f;
        for (int i = lane; i < D_INNER; i += 32) s += su[i] * w[i];
#pragma unroll
        for (int o = 16; o; o >>= 1) s += __shfl_down_sync(0xffffffffu, s, o);
        if (lane == 0) {
            if (j < D_STATE)          Bm[bl * D_STATE + j] = s + bB[j];
            else if (j < 2 * D_STATE) Cm[bl * D_STATE + (j - D_STATE)] = s + bC[j - D_STATE];
            else                      dtb[bl] = s + bdt[0];
        }
    }
}

// ---------------- selective scan: 2 threads per d -----------------------
// Fast path: A_log = log(1..16) tiled => dA_n = p^(n+1), p = 1/(1+e^x).
// OUT16: 0 -> bf16 hi/lo pair, 1 -> fp16 single (last layer).
template <int OUT16>
__global__ void scan_kernel(const float* __restrict__ U,
                            const float* __restrict__ RES,
                            const float* __restrict__ Bm,
                            const float* __restrict__ Cm,
                            const float* __restrict__ dtb,
                            const float* __restrict__ A_log,
                            const float* __restrict__ tau,
                            const float* __restrict__ Dp,
                            __nv_bfloat16* __restrict__ YRh,
                            __nv_bfloat16* __restrict__ YRl,
                            __half* __restrict__ YRf) {
    int td = blockIdx.x * 256 + threadIdx.x;
    int d = td >> 1;
    int half = td & 1;
    int b = blockIdx.y;

    float a[8], h[8];
    bool fast = true;
#pragma unroll
    for (int n = 0; n < 8; n++) {
        a[n] = -__expf(A_log[(size_t)d * D_STATE + half * 8 + n]);
        fast = fast && (fabsf(a[n] + (float)(half * 8 + n + 1)) < 1e-4f);
        h[n] = 0.f;
    }
    float tau_d = tau[d], dpv = Dp[d];
    size_t rowbase = (size_t)b * SEQ;

    for (int l = 0; l < SEQ; l++) {
        size_t bl = rowbase + l;
        float u = U[bl * D_INNER + d];
        const float* Bp = Bm + bl * D_STATE + half * 8;
        const float* Cp = Cm + bl * D_STATE + half * 8;
        float y0 = 0.f, y1 = 0.f;
        if (fast) {
            float x = tau_d + dtb[bl];
            float e = __expf(x);
            float delta = (x > 20.f) ? x : log1pf(e);
            float p = 1.f / (1.f + e);
            float du = delta * u;
            float q2 = p * p;
            float q3 = q2 * p,  q4 = q2 * q2;
            float q5 = q4 * p,  q6 = q4 * q2, q7 = q4 * q3, q8 = q4 * q4;
            float dA[8] = {p, q2, q3, q4, q5, q6, q7, q8};
            if (half) {
#pragma unroll
                for (int n = 0; n < 8; n++) dA[n] *= q8;
            }
#pragma unroll
            for (int n = 0; n < 8; n++) {
                h[n] = dA[n] * h[n] + du * Bp[n];
                float yy = Cp[n] * h[n];
                if (n & 1) y1 += yy; else y0 += yy;
            }
        } else {
            float delta = softplus_f(tau_d + dtb[bl]);
            float du = delta * u;
#pragma unroll
            for (int n = 0; n < 8; n++) {
                float da = __expf(delta * a[n]);
                h[n] = da * h[n] + du * Bp[n];
                float yy = Cp[n] * h[n];
                if (n & 1) y1 += yy; else y0 += yy;
            }
        }
        float y = y0 + y1;
        y += __shfl_xor_sync(0xffffffffu, y, 1);
        if (half == 0) {
            float v = (y + dpv * u) * RES[bl * D_INNER + d];
            if (OUT16) {
                YRf[bl * D_INNER + d] = __float2half(v);
            } else {
                __nv_bfloat16 hi, lo;
                split_bf16(v, hi, lo);
                YRh[bl * D_INNER + d] = hi;
                YRl[bl * D_INNER + d] = lo;
            }
        }
    }
}

// ---------------- bf16x3 HMMA GEMM 128x128: C = A*W^T -------------------
// EPI: 0 store fp32, 1 silu fp32, 2 accumulate fp32, 3 fp32 + bf16 hi/lo
#define HBM 128
#define HBN 128
#define HBK 32
#define HSTR 40
#define A_TILE (HBM * HSTR)
#define W_TILE (HBN * HSTR)
#define OFF_AH 0
#define OFF_AL (2 * A_TILE)
#define OFF_WH (4 * A_TILE)
#define OFF_WL (4 * A_TILE + 2 * W_TILE)
#define HG_SMEM ((4 * A_TILE + 4 * W_TILE) * 2)   // 81920 B

__device__ __forceinline__ void hfill(const __nv_bfloat16* __restrict__ Ah,
                                      const __nv_bfloat16* __restrict__ Al,
                                      const __nv_bfloat16* __restrict__ Wh,
                                      const __nv_bfloat16* __restrict__ Wl,
                                      int m0, int n0, int K, int k0,
                                      uint32_t smem_u, int stage, int tid) {
    uint32_t baseAh = smem_u + (OFF_AH + stage * A_TILE) * 2;
    uint32_t baseAl = smem_u + (OFF_AL + stage * A_TILE) * 2;
    uint32_t baseWh = smem_u + (OFF_WH + stage * W_TILE) * 2;
    uint32_t baseWl = smem_u + (OFF_WL + stage * W_TILE) * 2;
#pragma unroll
    for (int t = 0; t < 2; t++) {
        int idx = tid + t * 256;
        int r = idx >> 2, c = idx & 3;
        size_t go = (size_t)(m0 + r) * K + k0 + c * 8;
        uint32_t so = (uint32_t)(r * HSTR + c * 8) * 2;
        cp16(baseAh + so, Ah + go);
        cp16(baseAl + so, Al + go);
    }
#pragma unroll
    for (int t = 0; t < 2; t++) {
        int idx = tid + t * 256;
        int r = idx >> 2, c = idx & 3;
        size_t go = (size_t)(n0 + r) * K + k0 + c * 8;
        uint32_t so = (uint32_t)(r * HSTR + c * 8) * 2;
        cp16(baseWh + so, Wh + go);
        cp16(baseWl + so, Wl + go);
    }
}

template <int EPI>
__global__ void __launch_bounds__(256, 2) hgemm_kernel(
    const __nv_bfloat16* __restrict__ Ah, const __nv_bfloat16* __restrict__ Al,
    const __nv_bfloat16* __restrict__ Wh, const __nv_bfloat16* __restrict__ Wl,
    const float* __restrict__ bias, float* __restrict__ C,
    __nv_bfloat16* __restrict__ Chi, __nv_bfloat16* __restrict__ Clo,
    int M, int N, int K) {
    extern __shared__ __nv_bfloat16 hsm[];
    const uint32_t smem_u = smem_addr_u32(hsm);

    const int tid = threadIdx.x;
    const int wid = tid >> 5;
    const int lane = tid & 31;
    const int wm = wid & 3;
    const int wn = wid >> 2;
    const int m0 = blockIdx.y * HBM;
    const int n0 = blockIdx.x * HBN;

    const int arow = wm * 32 + (lane & 15);
    const int acol = (lane >> 4) * 8;
    const int brow = wn * 64 + (lane & 7) + ((lane >> 4) << 3);
    const int bcol = ((lane >> 3) & 1) * 8;

    float acc[2][8][4];
#pragma unroll
    for (int i = 0; i < 2; i++)
#pragma unroll
        for (int j = 0; j < 8; j++)
#pragma unroll
            for (int v = 0; v < 4; v++) acc[i][j][v] = 0.f;

    const int nb = K / HBK;
    hfill(Ah, Al, Wh, Wl, m0, n0, K, 0, smem_u, 0, tid);
    cp_commit();

    int buf = 0;
    for (int kb = 0; kb < nb; kb++) {
        if (kb + 1 < nb) {
            hfill(Ah, Al, Wh, Wl, m0, n0, K, (kb + 1) * HBK, smem_u, buf ^ 1, tid);
            cp_commit();
            cp_wait<1>();
        } else {
            cp_wait<0>();
        }
        __syncthreads();

        const uint32_t bAh = smem_u + (OFF_AH + buf * A_TILE) * 2;
        const uint32_t bAl = smem_u + (OFF_AL + buf * A_TILE) * 2;
        const uint32_t bWh = smem_u + (OFF_WH + buf * W_TILE) * 2;
        const uint32_t bWl = smem_u + (OFF_WL + buf * W_TILE) * 2;

#pragma unroll
        for (int kk = 0; kk < HBK; kk += 16) {
            uint32_t fah[2][4], fal[2][4];
#pragma unroll
            for (int mt = 0; mt < 2; mt++) {
                uint32_t off = (uint32_t)((arow + mt * 16) * HSTR + kk + acol) * 2;
                ldsm4(fah[mt][0], fah[mt][1], fah[mt][2], fah[mt][3], bAh + off);
                ldsm4(fal[mt][0], fal[mt][1], fal[mt][2], fal[mt][3], bAl + off);
            }
#pragma unroll
            for (int p = 0; p < 4; p++) {
                uint32_t bh[4], bl_[4];
                uint32_t off = (uint32_t)((brow + p * 16) * HSTR + kk + bcol) * 2;
                ldsm4(bh[0], bh[1], bh[2], bh[3], bWh + off);
                ldsm4(bl_[0], bl_[1], bl_[2], bl_[3], bWl + off);
#pragma unroll
                for (int mt = 0; mt < 2; mt++) {
                    float* d0 = acc[mt][p * 2];
                    float* d1 = acc[mt][p * 2 + 1];
                    mma_bf16(d0[0], d0[1], d0[2], d0[3],
                             fah[mt][0], fah[mt][1], fah[mt][2], fah[mt][3], bh[0], bh[1]);
                    mma_bf16(d0[0], d0[1], d0[2], d0[3],
                             fal[mt][0], fal[mt][1], fal[mt][2], fal[mt][3], bh[0], bh[1]);
                    mma_bf16(d0[0], d0[1], d0[2], d0[3],
                             fah[mt][0], fah[mt][1], fah[mt][2], fah[mt][3], bl_[0], bl_[1]);
                    mma_bf16(d1[0], d1[1], d1[2], d1[3],
                             fah[mt][0], fah[mt][1], fah[mt][2], fah[mt][3], bh[2], bh[3]);
                    mma_bf16(d1[0], d1[1], d1[2], d1[3],
                             fal[mt][0], fal[mt][1], fal[mt][2], fal[mt][3], bh[2], bh[3]);
                    mma_bf16(d1[0], d1[1], d1[2], d1[3],
                             fah[mt][0], fah[mt][1], fah[mt][2], fah[mt][3], bl_[2], bl_[3]);
                }
            }
        }
        __syncthreads();
        buf ^= 1;
    }

    const int g = lane >> 2, tg = lane & 3;
#pragma unroll
    for (int mt = 0; mt < 2; mt++) {
#pragma unroll
        for (int nt = 0; nt < 8; nt++) {
            int m = m0 + wm * 32 + mt * 16 + g;
            int n = n0 + wn * 64 + nt * 8 + tg * 2;
            float b0 = bias ? bias[n] : 0.f;
            float b1 = bias ? bias[n + 1] : 0.f;
#pragma unroll
            for (int half = 0; half < 2; half++) {
                int mm = m + half * 8;
                float v0 = acc[mt][nt][half * 2 + 0] + b0;
                float v1 = acc[mt][nt][half * 2 + 1] + b1;
                if (EPI == 1) { v0 = silu_f(v0); v1 = silu_f(v1); }
                size_t off = (size_t)mm * N + n;
                if (EPI == 2) { C[off] += v0; C[off + 1] += v1; }
                else          { C[off] = v0;  C[off + 1] = v1; }
                if (EPI == 3) {
                    __nv_bfloat16 h0, l0, h1, l1;
                    split_bf16(v0, h0, l0);
                    split_bf16(v1, h1, l1);
                    Chi[off] = h0; Chi[off + 1] = h1;
                    Clo[off] = l0; Clo[off + 1] = l1;
                }
            }
        }
    }
}

// ---------------- single-pass fp16 GEMM 128x128 --------------------------
// EPI: 0 store fp32, 1 silu fp32, 2 accumulate fp32, 3 fp32 + fp16 copy
#define F16_OFF_A 0
#define F16_OFF_W (2 * A_TILE)
#define F16_SMEM ((2 * A_TILE + 2 * W_TILE) * 2)   // 40960 B

__device__ __forceinline__ void ffill(const __half* __restrict__ A,
                                      const __half* __restrict__ W,
                                      int m0, int n0, int K, int k0,
                                      uint32_t smem_u, int stage, int tid) {
    uint32_t baseA = smem_u + (F16_OFF_A + stage * A_TILE) * 2;
    uint32_t baseW = smem_u + (F16_OFF_W + stage * W_TILE) * 2;
#pragma unroll
    for (int t = 0; t < 2; t++) {
        int idx = tid + t * 256;
        int r = idx >> 2, c = idx & 3;
        size_t go = (size_t)(m0 + r) * K + k0 + c * 8;
        uint32_t so = (uint32_t)(r * HSTR + c * 8) * 2;
        cp16(baseA + so, A + go);
    }
#pragma unroll
    for (int t = 0; t < 2; t++) {
        int idx = tid + t * 256;
        int r = idx >> 2, c = idx & 3;
        size_t go = (size_t)(n0 + r) * K + k0 + c * 8;
        uint32_t so = (uint32_t)(r * HSTR + c * 8) * 2;
        cp16(baseW + so, W + go);
    }
}

template <int EPI>
__global__ void __launch_bounds__(256, 2) fgemm_kernel(
    const __half* __restrict__ A, const __half* __restrict__ W,
    const float* __restrict__ bias, float* __restrict__ C,
    __half* __restrict__ Cf, int M, int N, int K) {
    extern __shared__ __half fsm[];
    const uint32_t smem_u = smem_addr_u32(fsm);

    const int tid = threadIdx.x;
    const int wid = tid >> 5;
    const int lane = tid & 31;
    const int wm = wid & 3;
    const int wn = wid >> 2;
    const int m0 = blockIdx.y * HBM;
    const int n0 = blockIdx.x * HBN;

    const int arow = wm * 32 + (lane & 15);
    const int acol = (lane >> 4) * 8;
    const int brow = wn * 64 + (lane & 7) + ((lane >> 4) << 3);
    const int bcol = ((lane >> 3) & 1) * 8;

    float acc[2][8][4];
#pragma unroll
    for (int i = 0; i < 2; i++)
#pragma unroll
        for (int j = 0; j < 8; j++)
#pragma unroll
            for (int v = 0; v < 4; v++) acc[i][j][v] = 0.f;

    const int nb = K / HBK;
    ffill(A, W, m0, n0, K, 0, smem_u, 0, tid);
    cp_commit();

    int buf = 0;
    for (int kb = 0; kb < nb; kb++) {
        if (kb + 1 < nb) {
            ffill(A, W, m0, n0, K, (kb + 1) * HBK, smem_u, buf ^ 1, tid);
            cp_commit();
            cp_wait<1>();
        } else {
            cp_wait<0>();
        }
        __syncthreads();

        const uint32_t bA = smem_u + (F16_OFF_A + buf * A_TILE) * 2;
        const uint32_t bW = smem_u + (F16_OFF_W + buf * W_TILE) * 2;

#pragma unroll
        for (int kk = 0; kk < HBK; kk += 16) {
            uint32_t fa[2][4];
#pragma unroll
            for (int mt = 0; mt < 2; mt++) {
                uint32_t off = (uint32_t)((arow + mt * 16) * HSTR + kk + acol) * 2;
                ldsm4(fa[mt][0], fa[mt][1], fa[mt][2], fa[mt][3], bA + off);
            }
#pragma unroll
            for (int p = 0; p < 4; p++) {
                uint32_t bh[4];
                uint32_t off = (uint32_t)((brow + p * 16) * HSTR + kk + bcol) * 2;
                ldsm4(bh[0], bh[1], bh[2], bh[3], bW + off);
#pragma unroll
                for (int mt = 0; mt < 2; mt++) {
                    float* d0 = acc[mt][p * 2];
                    float* d1 = acc[mt][p * 2 + 1];
                    mma_f16(d0[0], d0[1], d0[2], d0[3],
                            fa[mt][0], fa[mt][1], fa[mt][2], fa[mt][3], bh[0], bh[1]);
                    mma_f16(d1[0], d1[1], d1[2], d1[3],
                            fa[mt][0], fa[mt][1], fa[mt][2], fa[mt][3], bh[2], bh[3]);
                }
            }
        }
        __syncthreads();
        buf ^= 1;
    }

    const int g = lane >> 2, tg = lane & 3;
#pragma unroll
    for (int mt = 0; mt < 2; mt++) {
#pragma unroll
        for (int nt = 0; nt < 8; nt++) {
            int m = m0 + wm * 32 + mt * 16 + g;
            int n = n0 + wn * 64 + nt * 8 + tg * 2;
            float b0 = bias ? bias[n] : 0.f;
            float b1 = bias ? bias[n + 1] : 0.f;
#pragma unroll
            for (int half = 0; half < 2; half++) {
                int mm = m + half * 8;
                float v0 = acc[mt][nt][half * 2 + 0] + b0;
                float v1 = acc[mt][nt][half * 2 + 1] + b1;
                if (EPI == 1) { v0 = silu_f(v0); v1 = silu_f(v1); }
                size_t off = (size_t)mm * N + n;
                if (EPI == 2) { C[off] += v0; C[off + 1] += v1; }
                else          { C[off] = v0;  C[off + 1] = v1; }
                if (EPI == 3) {
                    Cf[off]     = __float2half(v0);
                    Cf[off + 1] = __float2half(v1);
                }
            }
        }
    }
}

// ---------------- launch ----------------
static inline void split_launch(const float* src, __nv_bfloat16* hi, __nv_bfloat16* lo, size_t n) {
    int n4 = (int)(n / 4);
    split_kernel<<<(n4 + 255) / 256, 256>>>((const float4*)src, (__nv_bfloat162*)hi,
                                            (__nv_bfloat162*)lo, n4);
}
static inline void cvt_launch(const float* src, __half* dst, size_t n) {
    int n4 = (int)(n / 4);
    cvt_f16_kernel<<<(n4 + 255) / 256, 256>>>((const float4*)src, (__half2*)dst, n4);
}

extern "C" void kernel_launch(void* const* d_in, const int* in_sizes, int n_in,
                              void* d_out, int out_size) {
    const float* emb    = (const float*)d_in[0];
    const float* norm_w = (const float*)d_in[1];
    const float* w_in   = (const float*)d_in[2];
    const float* b_in   = (const float*)d_in[3];
    const float* w_res  = (const float*)d_in[4];
    const float* b_res  = (const float*)d_in[5];
    const float* conv_w = (const float*)d_in[6];
    const float* conv_b = (const float*)d_in[7];
    const float* w_B    = (const float*)d_in[8];
    const float* b_B    = (const float*)d_in[9];
    const float* w_C    = (const float*)d_in[10];
    const float* b_C    = (const float*)d_in[11];
    const float* w_dt   = (const float*)d_in[12];
    const float* b_dt   = (const float*)d_in[13];
    const float* tau_dt = (const float*)d_in[14];
    const float* A_log  = (const float*)d_in[15];
    const float* Dp     = (const float*)d_in[16];
    const float* w_out  = (const float*)d_in[17];
    const float* b_out  = (const float*)d_in[18];
    const float* fnw    = (const float*)d_in[19];
    const int*   ids    = (const int*)d_in[20];
    float* out = (float*)d_out;

    cudaFuncSetAttribute(hgemm_kernel<1>, cudaFuncAttributeMaxDynamicSharedMemorySize, HG_SMEM);
    cudaFuncSetAttribute(hgemm_kernel<2>, cudaFuncAttributeMaxDynamicSharedMemorySize, HG_SMEM);
    cudaFuncSetAttribute(hgemm_kernel<3>, cudaFuncAttributeMaxDynamicSharedMemorySize, HG_SMEM);
    cudaFuncSetAttribute(fgemm_kernel<0>, cudaFuncAttributeMaxDynamicSharedMemorySize, F16_SMEM);
    cudaFuncSetAttribute(fgemm_kernel<1>, cudaFuncAttributeMaxDynamicSharedMemorySize, F16_SMEM);
    cudaFuncSetAttribute(fgemm_kernel<2>, cudaFuncAttributeMaxDynamicSharedMemorySize, F16_SMEM);
    cudaFuncSetAttribute(fgemm_kernel<3>, cudaFuncAttributeMaxDynamicSharedMemorySize, F16_SMEM);

    float *pX, *pH, *pRES, *pU, *pB, *pC, *pDT;
    cudaGetSymbolAddress((void**)&pX, g_X);
    cudaGetSymbolAddress((void**)&pH, g_H);
    cudaGetSymbolAddress((void**)&pRES, g_RES);
    cudaGetSymbolAddress((void**)&pU, g_U);
    cudaGetSymbolAddress((void**)&pB, g_B);
    cudaGetSymbolAddress((void**)&pC, g_C);
    cudaGetSymbolAddress((void**)&pDT, g_dt);

    __nv_bfloat16 *pXNh, *pXNl, *pHh, *pHl, *pYRh, *pYRl;
    __nv_bfloat16 *pWinh, *pWinl, *pWresh, *pWresl, *pWouth, *pWoutl;
    __half *pEmbF, *pXNf, *pHf, *pYRf, *pWinF, *pWresF, *pWoutF;
    cudaGetSymbolAddress((void**)&pXNh, g_XNh);  cudaGetSymbolAddress((void**)&pXNl, g_XNl);
    cudaGetSymbolAddress((void**)&pHh, g_Hh);    cudaGetSymbolAddress((void**)&pHl, g_Hl);
    cudaGetSymbolAddress((void**)&pYRh, g_YRh);  cudaGetSymbolAddress((void**)&pYRl, g_YRl);
    cudaGetSymbolAddress((void**)&pWinh, g_Winh);   cudaGetSymbolAddress((void**)&pWinl, g_Winl);
    cudaGetSymbolAddress((void**)&pWresh, g_Wresh); cudaGetSymbolAddress((void**)&pWresl, g_Wresl);
    cudaGetSymbolAddress((void**)&pWouth, g_Wouth); cudaGetSymbolAddress((void**)&pWoutl, g_Woutl);
    cudaGetSymbolAddress((void**)&pEmbF, g_EmbF);
    cudaGetSymbolAddress((void**)&pXNf, g_XNf);
    cudaGetSymbolAddress((void**)&pHf, g_Hf);
    cudaGetSymbolAddress((void**)&pYRf, g_YRf);
    cudaGetSymbolAddress((void**)&pWinF, g_WinF);
    cudaGetSymbolAddress((void**)&pWresF, g_WresF);
    cudaGetSymbolAddress((void**)&pWoutF, g_WoutF);

    // weight conversions: layers 0..2 bf16 hi/lo, layer 3 + emb fp16
    split_launch(w_in,  pWinh,  pWinl,  (size_t)3 * D_INNER * D_MODEL);
    split_launch(w_res, pWresh, pWresl, (size_t)3 * D_INNER * D_INNER);
    split_launch(w_out, pWouth, pWoutl, (size_t)3 * D_MODEL * D_INNER);
    cvt_launch(w_in  + (size_t)3 * D_INNER * D_MODEL, pWinF,  (size_t)D_INNER * D_MODEL);
    cvt_launch(w_res + (size_t)3 * D_INNER * D_INNER, pWresF, (size_t)D_INNER * D_INNER);
    cvt_launch(w_out + (size_t)3 * D_MODEL * D_INNER, pWoutF, (size_t)D_MODEL * D_INNER);
    cvt_launch(emb, pEmbF, (size_t)VOCAB * D_MODEL);

    embed_kernel<<<(M_ROWS * D_MODEL) / 256, 256>>>(emb, ids, pX);

    for (int i = 0; i < N_LAYER; i++) {
        const float* bi  = b_in   + (size_t)i * D_INNER;
        const float* br  = b_res  + (size_t)i * D_INNER;
        const float* cw  = conv_w + (size_t)i * D_INNER * D_CONV;
        const float* cb  = conv_b + (size_t)i * D_INNER;
        const float* wB  = w_B  + (size_t)i * D_STATE * D_INNER;
        const float* bB  = b_B  + (size_t)i * D_STATE;
        const float* wC  = w_C  + (size_t)i * D_STATE * D_INNER;
        const float* bC  = b_C  + (size_t)i * D_STATE;
        const float* wdt = w_dt + (size_t)i * D_INNER;
        const float* bdt = b_dt + (size_t)i;
        const float* tau = tau_dt + (size_t)i * D_INNER;
        const float* Al  = A_log + (size_t)i * D_INNER * D_STATE;
        const float* dp  = Dp    + (size_t)i * D_INNER;
        const float* bo  = b_out + (size_t)i * D_MODEL;
        const float* nw  = norm_w + (size_t)i * D_MODEL;

        if (i < 3) {
            const __nv_bfloat16* wih = pWinh  + (size_t)i * D_INNER * D_MODEL;
            const __nv_bfloat16* wil = pWinl  + (size_t)i * D_INNER * D_MODEL;
            const __nv_bfloat16* wrh = pWresh + (size_t)i * D_INNER * D_INNER;
            const __nv_bfloat16* wrl = pWresl + (size_t)i * D_INNER * D_INNER;
            const __nv_bfloat16* woh = pWouth + (size_t)i * D_MODEL * D_INNER;
            const __nv_bfloat16* wol = pWoutl + (size_t)i * D_MODEL * D_INNER;

            rmsnorm_kernel<<<M_ROWS, 256>>>(pX, nw, pXNh, pXNl);

            hgemm_kernel<3><<<dim3(D_INNER / HBN, M_ROWS / HBM), 256, HG_SMEM>>>(
                pXNh, pXNl, wih, wil, bi, pH, pHh, pHl, M_ROWS, D_INNER, D_MODEL);

            hgemm_kernel<1><<<dim3(D_INNER / HBN, M_ROWS / HBM), 256, HG_SMEM>>>(
                pHh, pHl, wrh, wrl, br, pRES, nullptr, nullptr, M_ROWS, D_INNER, D_INNER);

            conv_kernel<<<(M_ROWS * D_INNER) / 256, 256>>>(pH, cw, cb, pU);
            bc_kernel<<<M_ROWS, 256>>>(pU, wB, bB, wC, bC, wdt, bdt, pB, pC, pDT);

            scan_kernel<0><<<dim3(2 * D_INNER / 256, BATCH), 256>>>(
                pU, pRES, pB, pC, pDT, Al, tau, dp, pYRh, pYRl, nullptr);

            hgemm_kernel<2><<<dim3(D_MODEL / HBN, M_ROWS / HBM), 256, HG_SMEM>>>(
                pYRh, pYRl, woh, wol, bo, pX, nullptr, nullptr, M_ROWS, D_MODEL, D_INNER);
        } else {
            // last layer: fp16 single-pass GEMMs (terminal, no amplification)
            rmsnorm_f16_kernel<<<M_ROWS, 256>>>(pX, nw, pXNf);

            fgemm_kernel<3><<<dim3(D_INNER / HBN, M_ROWS / HBM), 256, F16_SMEM>>>(
                pXNf, pWinF, bi, pH, pHf, M_ROWS, D_INNER, D_MODEL);

            fgemm_kernel<1><<<dim3(D_INNER / HBN, M_ROWS / HBM), 256, F16_SMEM>>>(
                pHf, pWresF, br, pRES, nullptr, M_ROWS, D_INNER, D_INNER);

            conv_kernel<<<(M_ROWS * D_INNER) / 256, 256>>>(pH, cw, cb, pU);
            bc_kernel<<<M_ROWS, 256>>>(pU, wB, bB, wC, bC, wdt, bdt, pB, pC, pDT);

            scan_kernel<1><<<dim3(2 * D_INNER / 256, BATCH), 256>>>(
                pU, pRES, pB, pC, pDT, Al, tau, dp, nullptr, nullptr, pYRf);

            fgemm_kernel<2><<<dim3(D_MODEL / HBN, M_ROWS / HBM), 256, F16_SMEM>>>(
                pYRf, pWoutF, bo, pX, nullptr, M_ROWS, D_MODEL, D_INNER);
        }
    }

    rmsnorm_f16_kernel<<<M_ROWS, 256>>>(pX, fnw, pXNf);

    fgemm_kernel<0><<<dim3(VOCAB / HBN, M_ROWS / HBM), 256, F16_SMEM>>>(
        pXNf, pEmbF, nullptr, out, nullptr, M_ROWS, VOCAB, D_MODEL);
}

// round 16
// speedup vs baseline: 1.0926x; 1.0926x over previous
#include <cuda_runtime.h>
#include <cuda_bf16.h>
#include <cuda_fp16.h>
#include <cstdint>
#include <cstddef>

// ---------------- problem constants ----------------
#define D_MODEL 1024
#define N_LAYER 4
#define VOCAB   32000
#define D_STATE 16
#define D_INNER 2048
#define D_CONV  4
#define BATCH   2
#define SEQ     1024
#define M_ROWS  (BATCH * SEQ)     // 2048

// ---------------- scratch (device globals; no allocation allowed) ----------
__device__ float g_X  [M_ROWS * D_MODEL];
__device__ float g_H  [M_ROWS * D_INNER];
__device__ float g_RES[M_ROWS * D_INNER];
__device__ float g_U  [M_ROWS * D_INNER];
__device__ float g_B  [M_ROWS * D_STATE];
__device__ float g_C  [M_ROWS * D_STATE];
__device__ float g_dt [M_ROWS];
__device__ float g_Del[M_ROWS];
__device__ float g_P  [M_ROWS];

// bf16 hi/lo operand buffers (internal layers)
__device__ __nv_bfloat16 g_XNh[M_ROWS * D_MODEL], g_XNl[M_ROWS * D_MODEL];
__device__ __nv_bfloat16 g_Hh [M_ROWS * D_INNER], g_Hl [M_ROWS * D_INNER];
__device__ __nv_bfloat16 g_YRh[M_ROWS * D_INNER], g_YRl[M_ROWS * D_INNER];
__device__ __nv_bfloat16 g_Winh [N_LAYER * D_INNER * D_MODEL], g_Winl [N_LAYER * D_INNER * D_MODEL];
__device__ __nv_bfloat16 g_Wresh[N_LAYER * D_INNER * D_INNER], g_Wresl[N_LAYER * D_INNER * D_INNER];
__device__ __nv_bfloat16 g_Wouth[N_LAYER * D_MODEL * D_INNER], g_Woutl[N_LAYER * D_MODEL * D_INNER];

// fp16 buffers for single-pass lm_head
__device__ __half g_EmbF[(size_t)VOCAB * D_MODEL];
__device__ __half g_XNf [M_ROWS * D_MODEL];

// ---------------- small helpers ----------------
__device__ __forceinline__ float silu_f(float x) { return x / (1.f + __expf(-x)); }
__device__ __forceinline__ float softplus_f(float x) { return x > 20.f ? x : log1pf(__expf(x)); }

__device__ __forceinline__ uint32_t smem_addr_u32(const void* p) {
    uint32_t a;
    asm("{ .reg .u64 t; cvta.to.shared.u64 t, %1; cvt.u32.u64 %0, t; }" : "=r"(a) : "l"(p));
    return a;
}
__device__ __forceinline__ void cp16(uint32_t dst, const void* src) {
    asm volatile("cp.async.cg.shared.global [%0], [%1], 16;" :: "r"(dst), "l"(src));
}
__device__ __forceinline__ void cp_commit() {
    asm volatile("cp.async.commit_group;" ::: "memory");
}
template <int N>
__device__ __forceinline__ void cp_wait() {
    asm volatile("cp.async.wait_group %0;" :: "n"(N) : "memory");
}
__device__ __forceinline__ void ldsm4(uint32_t& r0, uint32_t& r1, uint32_t& r2, uint32_t& r3,
                                      uint32_t a) {
    asm volatile("ldmatrix.sync.aligned.m8n8.x4.shared.b16 {%0,%1,%2,%3}, [%4];"
                 : "=r"(r0), "=r"(r1), "=r"(r2), "=r"(r3) : "r"(a));
}
__device__ __forceinline__ void mma_bf16(float& d0, float& d1, float& d2, float& d3,
                                         uint32_t a0, uint32_t a1, uint32_t a2, uint32_t a3,
                                         uint32_t b0, uint32_t b1) {
    asm volatile(
        "mma.sync.aligned.m16n8k16.row.col.f32.bf16.bf16.f32 "
        "{%0,%1,%2,%3}, {%4,%5,%6,%7}, {%8,%9}, {%0,%1,%2,%3};"
        : "+f"(d0), "+f"(d1), "+f"(d2), "+f"(d3)
        : "r"(a0), "r"(a1), "r"(a2), "r"(a3), "r"(b0), "r"(b1));
}
__device__ __forceinline__ void mma_f16(float& d0, float& d1, float& d2, float& d3,
                                        uint32_t a0, uint32_t a1, uint32_t a2, uint32_t a3,
                                        uint32_t b0, uint32_t b1) {
    asm volatile(
        "mma.sync.aligned.m16n8k16.row.col.f32.f16.f16.f32 "
        "{%0,%1,%2,%3}, {%4,%5,%6,%7}, {%8,%9}, {%0,%1,%2,%3};"
        : "+f"(d0), "+f"(d1), "+f"(d2), "+f"(d3)
        : "r"(a0), "r"(a1), "r"(a2), "r"(a3), "r"(b0), "r"(b1));
}
__device__ __forceinline__ void split_bf16(float v, __nv_bfloat16& hi, __nv_bfloat16& lo) {
    hi = __float2bfloat16(v);
    lo = __float2bfloat16(v - __bfloat162float(hi));
}

// ---------------- fp32 -> bf16 hi/lo split (weights) --------------
__global__ void split_kernel(const float4* __restrict__ x,
                             __nv_bfloat162* __restrict__ hi,
                             __nv_bfloat162* __restrict__ lo, int n4) {
    int t = blockIdx.x * 256 + threadIdx.x;
    if (t >= n4) return;
    float4 v = x[t];
    __nv_bfloat16 a = __float2bfloat16(v.x), b = __float2bfloat16(v.y);
    __nv_bfloat16 c = __float2bfloat16(v.z), d = __float2bfloat16(v.w);
    hi[2 * t]     = __nv_bfloat162(a, b);
    hi[2 * t + 1] = __nv_bfloat162(c, d);
    lo[2 * t] = __nv_bfloat162(__float2bfloat16(v.x - __bfloat162float(a)),
                               __float2bfloat16(v.y - __bfloat162float(b)));
    lo[2 * t + 1] = __nv_bfloat162(__float2bfloat16(v.z - __bfloat162float(c)),
                                   __float2bfloat16(v.w - __bfloat162float(d)));
}

// ---------------- fp32 -> fp16 convert (embedding) --------------
__global__ void cvt_f16_kernel(const float4* __restrict__ x,
                               __half2* __restrict__ y, int n4) {
    int t = blockIdx.x * 256 + threadIdx.x;
    if (t >= n4) return;
    float4 v = x[t];
    y[2 * t]     = __floats2half2_rn(v.x, v.y);
    y[2 * t + 1] = __floats2half2_rn(v.z, v.w);
}

// ---------------- embedding gather ----------------
__global__ void embed_kernel(const float* __restrict__ emb,
                             const int* __restrict__ ids,
                             float* __restrict__ X) {
    int t = blockIdx.x * blockDim.x + threadIdx.x;
    int row = t >> 10, col = t & 1023;
    X[t] = emb[(size_t)ids[row] * D_MODEL + col];
}

// ---------------- rmsnorm -> bf16 hi/lo (internal layers) -------------
__global__ void rmsnorm_kernel(const float* __restrict__ X,
                               const float* __restrict__ w,
                               __nv_bfloat16* __restrict__ outh,
                               __nv_bfloat16* __restrict__ outl) {
    int row = blockIdx.x;
    const float* x = X + (size_t)row * D_MODEL;
    float s = 0.f;
    for (int i = threadIdx.x; i < D_MODEL; i += 256) { float v = x[i]; s += v * v; }
    __shared__ float red[256];
    red[threadIdx.x] = s;
    __syncthreads();
    for (int o = 128; o; o >>= 1) {
        if (threadIdx.x < o) red[threadIdx.x] += red[threadIdx.x + o];
        __syncthreads();
    }
    float scale = rsqrtf(red[0] * (1.f / D_MODEL) + 1e-5f);
    for (int i = threadIdx.x; i < D_MODEL; i += 256) {
        float v = x[i] * scale * w[i];
        __nv_bfloat16 hi, lo;
        split_bf16(v, hi, lo);
        outh[(size_t)row * D_MODEL + i] = hi;
        outl[(size_t)row * D_MODEL + i] = lo;
    }
}

// ---------------- rmsnorm -> fp16 (final, feeds lm_head) --------------
__global__ void rmsnorm_f16_kernel(const float* __restrict__ X,
                                   const float* __restrict__ w,
                                   __half* __restrict__ outf) {
    int row = blockIdx.x;
    const float* x = X + (size_t)row * D_MODEL;
    float s = 0.f;
    for (int i = threadIdx.x; i < D_MODEL; i += 256) { float v = x[i]; s += v * v; }
    __shared__ float red[256];
    red[threadIdx.x] = s;
    __syncthreads();
    for (int o = 128; o; o >>= 1) {
        if (threadIdx.x < o) red[threadIdx.x] += red[threadIdx.x + o];
        __syncthreads();
    }
    float scale = rsqrtf(red[0] * (1.f / D_MODEL) + 1e-5f);
    for (int i = threadIdx.x; i < D_MODEL; i += 256)
        outf[(size_t)row * D_MODEL + i] = __float2half(x[i] * scale * w[i]);
}

// ---------------- depthwise causal conv + silu ----------------
__global__ void conv_kernel(const float* __restrict__ H,
                            const float* __restrict__ cw,
                            const float* __restrict__ cb,
                            float* __restrict__ Uo) {
    int t = blockIdx.x * blockDim.x + threadIdx.x;
    int d = t & (D_INNER - 1);
    int bl = t >> 11;
    int l = bl & (SEQ - 1);
    float acc = cb[d];
#pragma unroll
    for (int j = 0; j < D_CONV; j++) {
        int ll = l - (D_CONV - 1) + j;
        if (ll >= 0)
            acc += H[(size_t)(bl - l + ll) * D_INNER + d] * cw[d * D_CONV + j];
    }
    Uo[t] = silu_f(acc);
}

// ---------------- B, C, dt projections ----------------
__global__ void bc_kernel(const float* __restrict__ U,
                          const float* __restrict__ wB, const float* __restrict__ bB,
                          const float* __restrict__ wC, const float* __restrict__ bC,
                          const float* __restrict__ wdt, const float* __restrict__ bdt,
                          float* __restrict__ Bm, float* __restrict__ Cm,
                          float* __restrict__ dtb) {
    int bl = blockIdx.x;
    __shared__ float su[D_INNER];
    const float* u = U + (size_t)bl * D_INNER;
    for (int i = threadIdx.x; i < D_INNER; i += 256) su[i] = u[i];
    __syncthreads();
    int warp = threadIdx.x >> 5, lane = threadIdx.x & 31;
    for (int j = warp; j < 2 * D_STATE + 1; j += 8) {
        const float* w = (j < D_STATE) ? wB + (size_t)j * D_INNER
                       : (j < 2 * D_STATE) ? wC + (size_t)(j - D_STATE) * D_INNER
                       : wdt;
        float s = 0.f;
        for (int i = lane; i < D_INNER; i += 32) s += su[i] * w[i];
#pragma unroll
        for (int o = 16; o; o >>= 1) s += __shfl_down_sync(0xffffffffu, s, o);
        if (lane == 0) {
            if (j < D_STATE)          Bm[bl * D_STATE + j] = s + bB[j];
            else if (j < 2 * D_STATE) Cm[bl * D_STATE + (j - D_STATE)] = s + bC[j - D_STATE];
            else                      dtb[bl] = s + bdt[0];
        }
    }
}

// ---------------- per-token delta/p precompute (tau == 0 fast path) -----
__global__ void dt_kernel(const float* __restrict__ dtb,
                          float* __restrict__ Del, float* __restrict__ P) {
    int bl = blockIdx.x * 256 + threadIdx.x;
    if (bl >= M_ROWS) return;
    float x = dtb[bl];
    float e = __expf(x);
    Del[bl] = (x > 20.f) ? x : log1pf(e);
    P[bl]   = 1.f / (1.f + e);        // = exp(-softplus(x)), exactly
}

// ---------------- selective scan: 2 threads per d -----------------------
// Fast path (guarded): A_log = log(1..16) tiled AND tau == 0 =>
// dA_n = p^(n+1) with per-token p precomputed -> zero transcendentals.
__global__ void scan_kernel(const float* __restrict__ U,
                            const float* __restrict__ RES,
                            const float* __restrict__ Bm,
                            const float* __restrict__ Cm,
                            const float* __restrict__ dtb,
                            const float* __restrict__ Del,
                            const float* __restrict__ P,
                            const float* __restrict__ A_log,
                            const float* __restrict__ tau,
                            const float* __restrict__ Dp,
                            __nv_bfloat16* __restrict__ YRh,
                            __nv_bfloat16* __restrict__ YRl) {
    int td = blockIdx.x * 256 + threadIdx.x;
    int d = td >> 1;
    int half = td & 1;
    int b = blockIdx.y;

    float a[8], h[8];
    bool fast = true;
#pragma unroll
    for (int n = 0; n < 8; n++) {
        a[n] = -__expf(A_log[(size_t)d * D_STATE + half * 8 + n]);
        fast = fast && (fabsf(a[n] + (float)(half * 8 + n + 1)) < 1e-4f);
        h[n] = 0.f;
    }
    float tau_d = tau[d], dpv = Dp[d];
    fast = fast && (tau_d == 0.f);
    size_t rowbase = (size_t)b * SEQ;

    if (fast) {
        for (int l = 0; l < SEQ; l++) {
            size_t bl = rowbase + l;
            float delta = Del[bl];
            float p = P[bl];
            float u = U[bl * D_INNER + d];
            float du = delta * u;
            const float* Bp = Bm + bl * D_STATE + half * 8;
            const float* Cp = Cm + bl * D_STATE + half * 8;
            float q2 = p * p;
            float q3 = q2 * p,  q4 = q2 * q2;
            float q5 = q4 * p,  q6 = q4 * q2, q7 = q4 * q3, q8 = q4 * q4;
            float dA[8] = {p, q2, q3, q4, q5, q6, q7, q8};
            if (half) {
#pragma unroll
                for (int n = 0; n < 8; n++) dA[n] *= q8;
            }
            float y0 = 0.f, y1 = 0.f;
#pragma unroll
            for (int n = 0; n < 8; n++) {
                h[n] = dA[n] * h[n] + du * Bp[n];
                float yy = Cp[n] * h[n];
                if (n & 1) y1 += yy; else y0 += yy;
            }
            float y = y0 + y1;
            y += __shfl_xor_sync(0xffffffffu, y, 1);
            if (half == 0) {
                float v = (y + dpv * u) * RES[bl * D_INNER + d];
                __nv_bfloat16 hi, lo;
                split_bf16(v, hi, lo);
                YRh[bl * D_INNER + d] = hi;
                YRl[bl * D_INNER + d] = lo;
            }
        }
    } else {
        for (int l = 0; l < SEQ; l++) {
            size_t bl = rowbase + l;
            float delta = softplus_f(tau_d + dtb[bl]);
            float u = U[bl * D_INNER + d];
            float du = delta * u;
            const float* Bp = Bm + bl * D_STATE + half * 8;
            const float* Cp = Cm + bl * D_STATE + half * 8;
            float y0 = 0.f, y1 = 0.f;
#pragma unroll
            for (int n = 0; n < 8; n++) {
                float da = __expf(delta * a[n]);
                h[n] = da * h[n] + du * Bp[n];
                float yy = Cp[n] * h[n];
                if (n & 1) y1 += yy; else y0 += yy;
            }
            float y = y0 + y1;
            y += __shfl_xor_sync(0xffffffffu, y, 1);
            if (half == 0) {
                float v = (y + dpv * u) * RES[bl * D_INNER + d];
                __nv_bfloat16 hi, lo;
                split_bf16(v, hi, lo);
                YRh[bl * D_INNER + d] = hi;
                YRl[bl * D_INNER + d] = lo;
            }
        }
    }
}

// ---------------- bf16x3 HMMA GEMM 128x128: C = A*W^T -------------------
// EPI: 0 store fp32, 1 silu fp32, 2 accumulate fp32, 3 fp32 + bf16 hi/lo
#define HBM 128
#define HBN 128
#define HBK 32
#define HSTR 40
#define A_TILE (HBM * HSTR)
#define W_TILE (HBN * HSTR)
#define OFF_AH 0
#define OFF_AL (2 * A_TILE)
#define OFF_WH (4 * A_TILE)
#define OFF_WL (4 * A_TILE + 2 * W_TILE)
#define HG_SMEM ((4 * A_TILE + 4 * W_TILE) * 2)   // 81920 B

__device__ __forceinline__ void hfill(const __nv_bfloat16* __restrict__ Ah,
                                      const __nv_bfloat16* __restrict__ Al,
                                      const __nv_bfloat16* __restrict__ Wh,
                                      const __nv_bfloat16* __restrict__ Wl,
                                      int m0, int n0, int K, int k0,
                                      uint32_t smem_u, int stage, int tid) {
    uint32_t baseAh = smem_u + (OFF_AH + stage * A_TILE) * 2;
    uint32_t baseAl = smem_u + (OFF_AL + stage * A_TILE) * 2;
    uint32_t baseWh = smem_u + (OFF_WH + stage * W_TILE) * 2;
    uint32_t baseWl = smem_u + (OFF_WL + stage * W_TILE) * 2;
#pragma unroll
    for (int t = 0; t < 2; t++) {
        int idx = tid + t * 256;
        int r = idx >> 2, c = idx & 3;
        size_t go = (size_t)(m0 + r) * K + k0 + c * 8;
        uint32_t so = (uint32_t)(r * HSTR + c * 8) * 2;
        cp16(baseAh + so, Ah + go);
        cp16(baseAl + so, Al + go);
    }
#pragma unroll
    for (int t = 0; t < 2; t++) {
        int idx = tid + t * 256;
        int r = idx >> 2, c = idx & 3;
        size_t go = (size_t)(n0 + r) * K + k0 + c * 8;
        uint32_t so = (uint32_t)(r * HSTR + c * 8) * 2;
        cp16(baseWh + so, Wh + go);
        cp16(baseWl + so, Wl + go);
    }
}

template <int EPI>
__global__ void __launch_bounds__(256, 2) hgemm_kernel(
    const __nv_bfloat16* __restrict__ Ah, const __nv_bfloat16* __restrict__ Al,
    const __nv_bfloat16* __restrict__ Wh, const __nv_bfloat16* __restrict__ Wl,
    const float* __restrict__ bias, float* __restrict__ C,
    __nv_bfloat16* __restrict__ Chi, __nv_bfloat16* __restrict__ Clo,
    int M, int N, int K) {
    extern __shared__ __nv_bfloat16 hsm[];
    const uint32_t smem_u = smem_addr_u32(hsm);

    const int tid = threadIdx.x;
    const int wid = tid >> 5;
    const int lane = tid & 31;
    const int wm = wid & 3;
    const int wn = wid >> 2;
    const int m0 = blockIdx.y * HBM;
    const int n0 = blockIdx.x * HBN;

    const int arow = wm * 32 + (lane & 15);
    const int acol = (lane >> 4) * 8;
    const int brow = wn * 64 + (lane & 7) + ((lane >> 4) << 3);
    const int bcol = ((lane >> 3) & 1) * 8;

    float acc[2][8][4];
#pragma unroll
    for (int i = 0; i < 2; i++)
#pragma unroll
        for (int j = 0; j < 8; j++)
#pragma unroll
            for (int v = 0; v < 4; v++) acc[i][j][v] = 0.f;

    const int nb = K / HBK;
    hfill(Ah, Al, Wh, Wl, m0, n0, K, 0, smem_u, 0, tid);
    cp_commit();

    int buf = 0;
    for (int kb = 0; kb < nb; kb++) {
        if (kb + 1 < nb) {
            hfill(Ah, Al, Wh, Wl, m0, n0, K, (kb + 1) * HBK, smem_u, buf ^ 1, tid);
            cp_commit();
            cp_wait<1>();
        } else {
            cp_wait<0>();
        }
        __syncthreads();

        const uint32_t bAh = smem_u + (OFF_AH + buf * A_TILE) * 2;
        const uint32_t bAl = smem_u + (OFF_AL + buf * A_TILE) * 2;
        const uint32_t bWh = smem_u + (OFF_WH + buf * W_TILE) * 2;
        const uint32_t bWl = smem_u + (OFF_WL + buf * W_TILE) * 2;

#pragma unroll
        for (int kk = 0; kk < HBK; kk += 16) {
            uint32_t fah[2][4], fal[2][4];
#pragma unroll
            for (int mt = 0; mt < 2; mt++) {
                uint32_t off = (uint32_t)((arow + mt * 16) * HSTR + kk + acol) * 2;
                ldsm4(fah[mt][0], fah[mt][1], fah[mt][2], fah[mt][3], bAh + off);
                ldsm4(fal[mt][0], fal[mt][1], fal[mt][2], fal[mt][3], bAl + off);
            }
#pragma unroll
            for (int p = 0; p < 4; p++) {
                uint32_t bh[4], bl_[4];
                uint32_t off = (uint32_t)((brow + p * 16) * HSTR + kk + bcol) * 2;
                ldsm4(bh[0], bh[1], bh[2], bh[3], bWh + off);
                ldsm4(bl_[0], bl_[1], bl_[2], bl_[3], bWl + off);
#pragma unroll
                for (int mt = 0; mt < 2; mt++) {
                    float* d0 = acc[mt][p * 2];
                    float* d1 = acc[mt][p * 2 + 1];
                    mma_bf16(d0[0], d0[1], d0[2], d0[3],
                             fah[mt][0], fah[mt][1], fah[mt][2], fah[mt][3], bh[0], bh[1]);
                    mma_bf16(d0[0], d0[1], d0[2], d0[3],
                             fal[mt][0], fal[mt][1], fal[mt][2], fal[mt][3], bh[0], bh[1]);
                    mma_bf16(d0[0], d0[1], d0[2], d0[3],
                             fah[mt][0], fah[mt][1], fah[mt][2], fah[mt][3], bl_[0], bl_[1]);
                    mma_bf16(d1[0], d1[1], d1[2], d1[3],
                             fah[mt][0], fah[mt][1], fah[mt][2], fah[mt][3], bh[2], bh[3]);
                    mma_bf16(d1[0], d1[1], d1[2], d1[3],
                             fal[mt][0], fal[mt][1], fal[mt][2], fal[mt][3], bh[2], bh[3]);
                    mma_bf16(d1[0], d1[1], d1[2], d1[3],
                             fah[mt][0], fah[mt][1], fah[mt][2], fah[mt][3], bl_[2], bl_[3]);
                }
            }
        }
        __syncthreads();
        buf ^= 1;
    }

    const int g = lane >> 2, tg = lane & 3;
#pragma unroll
    for (int mt = 0; mt < 2; mt++) {
#pragma unroll
        for (int nt = 0; nt < 8; nt++) {
            int m = m0 + wm * 32 + mt * 16 + g;
            int n = n0 + wn * 64 + nt * 8 + tg * 2;
            float b0 = bias ? bias[n] : 0.f;
            float b1 = bias ? bias[n + 1] : 0.f;
#pragma unroll
            for (int half = 0; half < 2; half++) {
                int mm = m + half * 8;
                float v0 = acc[mt][nt][half * 2 + 0] + b0;
                float v1 = acc[mt][nt][half * 2 + 1] + b1;
                if (EPI == 1) { v0 = silu_f(v0); v1 = silu_f(v1); }
                size_t off = (size_t)mm * N + n;
                if (EPI == 2) { C[off] += v0; C[off + 1] += v1; }
                else          { C[off] = v0;  C[off + 1] = v1; }
                if (EPI == 3) {
                    __nv_bfloat16 h0, l0, h1, l1;
                    split_bf16(v0, h0, l0);
                    split_bf16(v1, h1, l1);
                    Chi[off] = h0; Chi[off + 1] = h1;
                    Clo[off] = l0; Clo[off + 1] = l1;
                }
            }
        }
    }
}

// ---------------- single-pass fp16 GEMM 128x128 (lm_head) ---------------
#define F16_OFF_A 0
#define F16_OFF_W (2 * A_TILE)
#define F16_SMEM ((2 * A_TILE + 2 * W_TILE) * 2)   // 40960 B

__device__ __forceinline__ void ffill(const __half* __restrict__ A,
                                      const __half* __restrict__ W,
                                      int m0, int n0, int K, int k0,
                                      uint32_t smem_u, int stage, int tid) {
    uint32_t baseA = smem_u + (F16_OFF_A + stage * A_TILE) * 2;
    uint32_t baseW = smem_u + (F16_OFF_W + stage * W_TILE) * 2;
#pragma unroll
    for (int t = 0; t < 2; t++) {
        int idx = tid + t * 256;
        int r = idx >> 2, c = idx & 3;
        size_t go = (size_t)(m0 + r) * K + k0 + c * 8;
        uint32_t so = (uint32_t)(r * HSTR + c * 8) * 2;
        cp16(baseA + so, A + go);
    }
#pragma unroll
    for (int t = 0; t < 2; t++) {
        int idx = tid + t * 256;
        int r = idx >> 2, c = idx & 3;
        size_t go = (size_t)(n0 + r) * K + k0 + c * 8;
        uint32_t so = (uint32_t)(r * HSTR + c * 8) * 2;
        cp16(baseW + so, W + go);
    }
}

__global__ void __launch_bounds__(256, 2) fgemm_kernel(
    const __half* __restrict__ A, const __half* __restrict__ W,
    float* __restrict__ C, int M, int N, int K) {
    extern __shared__ __half fsm[];
    const uint32_t smem_u = smem_addr_u32(fsm);

    const int tid = threadIdx.x;
    const int wid = tid >> 5;
    const int lane = tid & 31;
    const int wm = wid & 3;
    const int wn = wid >> 2;
    const int m0 = blockIdx.y * HBM;
    const int n0 = blockIdx.x * HBN;

    const int arow = wm * 32 + (lane & 15);
    const int acol = (lane >> 4) * 8;
    const int brow = wn * 64 + (lane & 7) + ((lane >> 4) << 3);
    const int bcol = ((lane >> 3) & 1) * 8;

    float acc[2][8][4];
#pragma unroll
    for (int i = 0; i < 2; i++)
#pragma unroll
        for (int j = 0; j < 8; j++)
#pragma unroll
            for (int v = 0; v < 4; v++) acc[i][j][v] = 0.f;

    const int nb = K / HBK;
    ffill(A, W, m0, n0, K, 0, smem_u, 0, tid);
    cp_commit();

    int buf = 0;
    for (int kb = 0; kb < nb; kb++) {
        if (kb + 1 < nb) {
            ffill(A, W, m0, n0, K, (kb + 1) * HBK, smem_u, buf ^ 1, tid);
            cp_commit();
            cp_wait<1>();
        } else {
            cp_wait<0>();
        }
        __syncthreads();

        const uint32_t bA = smem_u + (F16_OFF_A + buf * A_TILE) * 2;
        const uint32_t bW = smem_u + (F16_OFF_W + buf * W_TILE) * 2;

#pragma unroll
        for (int kk = 0; kk < HBK; kk += 16) {
            uint32_t fa[2][4];
#pragma unroll
            for (int mt = 0; mt < 2; mt++) {
                uint32_t off = (uint32_t)((arow + mt * 16) * HSTR + kk + acol) * 2;
                ldsm4(fa[mt][0], fa[mt][1], fa[mt][2], fa[mt][3], bA + off);
            }
#pragma unroll
            for (int p = 0; p < 4; p++) {
                uint32_t bh[4];
                uint32_t off = (uint32_t)((brow + p * 16) * HSTR + kk + bcol) * 2;
                ldsm4(bh[0], bh[1], bh[2], bh[3], bW + off);
#pragma unroll
                for (int mt = 0; mt < 2; mt++) {
                    float* d0 = acc[mt][p * 2];
                    float* d1 = acc[mt][p * 2 + 1];
                    mma_f16(d0[0], d0[1], d0[2], d0[3],
                            fa[mt][0], fa[mt][1], fa[mt][2], fa[mt][3], bh[0], bh[1]);
                    mma_f16(d1[0], d1[1], d1[2], d1[3],
                            fa[mt][0], fa[mt][1], fa[mt][2], fa[mt][3], bh[2], bh[3]);
                }
            }
        }
        __syncthreads();
        buf ^= 1;
    }

    const int g = lane >> 2, tg = lane & 3;
#pragma unroll
    for (int mt = 0; mt < 2; mt++) {
#pragma unroll
        for (int nt = 0; nt < 8; nt++) {
            int m = m0 + wm * 32 + mt * 16 + g;
            int n = n0 + wn * 64 + nt * 8 + tg * 2;
#pragma unroll
            for (int half = 0; half < 2; half++) {
                int mm = m + half * 8;
                size_t off = (size_t)mm * N + n;
                C[off]     = acc[mt][nt][half * 2 + 0];
                C[off + 1] = acc[mt][nt][half * 2 + 1];
            }
        }
    }
}

// ---------------- launch ----------------
static inline void split_launch(const float* src, __nv_bfloat16* hi, __nv_bfloat16* lo, size_t n) {
    int n4 = (int)(n / 4);
    split_kernel<<<(n4 + 255) / 256, 256>>>((const float4*)src, (__nv_bfloat162*)hi,
                                            (__nv_bfloat162*)lo, n4);
}

extern "C" void kernel_launch(void* const* d_in, const int* in_sizes, int n_in,
                              void* d_out, int out_size) {
    const float* emb    = (const float*)d_in[0];
    const float* norm_w = (const float*)d_in[1];
    const float* w_in   = (const float*)d_in[2];
    const float* b_in   = (const float*)d_in[3];
    const float* w_res  = (const float*)d_in[4];
    const float* b_res  = (const float*)d_in[5];
    const float* conv_w = (const float*)d_in[6];
    const float* conv_b = (const float*)d_in[7];
    const float* w_B    = (const float*)d_in[8];
    const float* b_B    = (const float*)d_in[9];
    const float* w_C    = (const float*)d_in[10];
    const float* b_C    = (const float*)d_in[11];
    const float* w_dt   = (const float*)d_in[12];
    const float* b_dt   = (const float*)d_in[13];
    const float* tau_dt = (const float*)d_in[14];
    const float* A_log  = (const float*)d_in[15];
    const float* Dp     = (const float*)d_in[16];
    const float* w_out  = (const float*)d_in[17];
    const float* b_out  = (const float*)d_in[18];
    const float* fnw    = (const float*)d_in[19];
    const int*   ids    = (const int*)d_in[20];
    float* out = (float*)d_out;

    cudaFuncSetAttribute(hgemm_kernel<1>, cudaFuncAttributeMaxDynamicSharedMemorySize, HG_SMEM);
    cudaFuncSetAttribute(hgemm_kernel<2>, cudaFuncAttributeMaxDynamicSharedMemorySize, HG_SMEM);
    cudaFuncSetAttribute(hgemm_kernel<3>, cudaFuncAttributeMaxDynamicSharedMemorySize, HG_SMEM);
    cudaFuncSetAttribute(fgemm_kernel, cudaFuncAttributeMaxDynamicSharedMemorySize, F16_SMEM);

    float *pX, *pH, *pRES, *pU, *pB, *pC, *pDT, *pDel, *pP;
    cudaGetSymbolAddress((void**)&pX, g_X);
    cudaGetSymbolAddress((void**)&pH, g_H);
    cudaGetSymbolAddress((void**)&pRES, g_RES);
    cudaGetSymbolAddress((void**)&pU, g_U);
    cudaGetSymbolAddress((void**)&pB, g_B);
    cudaGetSymbolAddress((void**)&pC, g_C);
    cudaGetSymbolAddress((void**)&pDT, g_dt);
    cudaGetSymbolAddress((void**)&pDel, g_Del);
    cudaGetSymbolAddress((void**)&pP, g_P);

    __nv_bfloat16 *pXNh, *pXNl, *pHh, *pHl, *pYRh, *pYRl;
    __nv_bfloat16 *pWinh, *pWinl, *pWresh, *pWresl, *pWouth, *pWoutl;
    __half *pEmbF, *pXNf;
    cudaGetSymbolAddress((void**)&pXNh, g_XNh);  cudaGetSymbolAddress((void**)&pXNl, g_XNl);
    cudaGetSymbolAddress((void**)&pHh, g_Hh);    cudaGetSymbolAddress((void**)&pHl, g_Hl);
    cudaGetSymbolAddress((void**)&pYRh, g_YRh);  cudaGetSymbolAddress((void**)&pYRl, g_YRl);
    cudaGetSymbolAddress((void**)&pWinh, g_Winh);   cudaGetSymbolAddress((void**)&pWinl, g_Winl);
    cudaGetSymbolAddress((void**)&pWresh, g_Wresh); cudaGetSymbolAddress((void**)&pWresl, g_Wresl);
    cudaGetSymbolAddress((void**)&pWouth, g_Wouth); cudaGetSymbolAddress((void**)&pWoutl, g_Woutl);
    cudaGetSymbolAddress((void**)&pEmbF, g_EmbF);
    cudaGetSymbolAddress((void**)&pXNf, g_XNf);

    // weight conversions (all layers at once)
    split_launch(w_in,  pWinh,  pWinl,  (size_t)N_LAYER * D_INNER * D_MODEL);
    split_launch(w_res, pWresh, pWresl, (size_t)N_LAYER * D_INNER * D_INNER);
    split_launch(w_out, pWouth, pWoutl, (size_t)N_LAYER * D_MODEL * D_INNER);
    {
        int n4 = (int)((size_t)VOCAB * D_MODEL / 4);
        cvt_f16_kernel<<<(n4 + 255) / 256, 256>>>((const float4*)emb, (__half2*)pEmbF, n4);
    }

    embed_kernel<<<(M_ROWS * D_MODEL) / 256, 256>>>(emb, ids, pX);

    for (int i = 0; i < N_LAYER; i++) {
        const float* bi  = b_in   + (size_t)i * D_INNER;
        const float* br  = b_res  + (size_t)i * D_INNER;
        const float* cw  = conv_w + (size_t)i * D_INNER * D_CONV;
        const float* cb  = conv_b + (size_t)i * D_INNER;
        const float* wB  = w_B  + (size_t)i * D_STATE * D_INNER;
        const float* bB  = b_B  + (size_t)i * D_STATE;
        const float* wC  = w_C  + (size_t)i * D_STATE * D_INNER;
        const float* bC  = b_C  + (size_t)i * D_STATE;
        const float* wdt = w_dt + (size_t)i * D_INNER;
        const float* bdt = b_dt + (size_t)i;
        const float* tau = tau_dt + (size_t)i * D_INNER;
        const float* Al  = A_log + (size_t)i * D_INNER * D_STATE;
        const float* dp  = Dp    + (size_t)i * D_INNER;
        const float* bo  = b_out + (size_t)i * D_MODEL;
        const float* nw  = norm_w + (size_t)i * D_MODEL;
        const __nv_bfloat16* wih = pWinh  + (size_t)i * D_INNER * D_MODEL;
        const __nv_bfloat16* wil = pWinl  + (size_t)i * D_INNER * D_MODEL;
        const __nv_bfloat16* wrh = pWresh + (size_t)i * D_INNER * D_INNER;
        const __nv_bfloat16* wrl = pWresl + (size_t)i * D_INNER * D_INNER;
        const __nv_bfloat16* woh = pWouth + (size_t)i * D_MODEL * D_INNER;
        const __nv_bfloat16* wol = pWoutl + (size_t)i * D_MODEL * D_INNER;

        rmsnorm_kernel<<<M_ROWS, 256>>>(pX, nw, pXNh, pXNl);

        hgemm_kernel<3><<<dim3(D_INNER / HBN, M_ROWS / HBM), 256, HG_SMEM>>>(
            pXNh, pXNl, wih, wil, bi, pH, pHh, pHl, M_ROWS, D_INNER, D_MODEL);

        hgemm_kernel<1><<<dim3(D_INNER / HBN, M_ROWS / HBM), 256, HG_SMEM>>>(
            pHh, pHl, wrh, wrl, br, pRES, nullptr, nullptr, M_ROWS, D_INNER, D_INNER);

        conv_kernel<<<(M_ROWS * D_INNER) / 256, 256>>>(pH, cw, cb, pU);
        bc_kernel<<<M_ROWS, 256>>>(pU, wB, bB, wC, bC, wdt, bdt, pB, pC, pDT);
        dt_kernel<<<M_ROWS / 256, 256>>>(pDT, pDel, pP);

        scan_kernel<<<dim3(2 * D_INNER / 256, BATCH), 256>>>(
            pU, pRES, pB, pC, pDT, pDel, pP, Al, tau, dp, pYRh, pYRl);

        hgemm_kernel<2><<<dim3(D_MODEL / HBN, M_ROWS / HBM), 256, HG_SMEM>>>(
            pYRh, pYRl, woh, wol, bo, pX, nullptr, nullptr, M_ROWS, D_MODEL, D_INNER);
    }

    rmsnorm_f16_kernel<<<M_ROWS, 256>>>(pX, fnw, pXNf);

    fgemm_kernel<<<dim3(VOCAB / HBN, M_ROWS / HBM), 256, F16_SMEM>>>(
        pXNf, pEmbF, out, M_ROWS, VOCAB, D_MODEL);
}